// round 15
// baseline (speedup 1.0000x reference)
#include <cuda_runtime.h>
#include <cuda_fp16.h>
#include <cstdint>

#define N_NODES 50000
#define N_EDGES 800000
#define IN_CH 16
#define OUT_CH 16
#define M_TILE 224
#define NT_TILES ((N_EDGES + M_TILE - 1) / M_TILE)   // 3572
#define THREADS 448
#define GRID 152

// ---- smem byte offsets ----
#define SM_W1   0        // [16][120] f16   = 3840
#define SM_W2   3840     // [112][120] f16  = 26880
#define SM_W3   30720    // [112][120] f16  = 26880
#define SM_W4   57600    // [112][264] f16  = 59136
#define SM_A0   116736   // [224][24] f16   = 10752
#define SM_XV   127488   // [224][20] f32   = 17920
#define SM_B1   145408   // [112] f32
#define SM_B2   145856
#define SM_B3   146304
#define SM_B4   146752   // [256] f32
#define SMEM_BYTES 147776
#define W_ZERO_U32 (116736 / 4)

__device__ float g_agg[N_NODES * OUT_CH];
__device__ float g_cnt[N_NODES];

__device__ __forceinline__ uint32_t smem_u32(const void* p) {
    uint32_t a;
    asm("{ .reg .u64 t; cvta.to.shared.u64 t, %1; cvt.u32.u64 %0, t; }" : "=r"(a) : "l"(p));
    return a;
}
__device__ __forceinline__ uint32_t pack_relu2(float a, float b) {
    __half2 h = __floats2half2_rn(fmaxf(a, 0.f), fmaxf(b, 0.f));
    return *(uint32_t*)&h;
}

#define LDSM_X2(r, a) \
    asm volatile("ldmatrix.sync.aligned.m8n8.x2.shared.b16 {%0,%1}, [%2];" \
        : "=r"((r)[0]), "=r"((r)[1]) : "r"(a))
#define LDSM_X2T(r, a) \
    asm volatile("ldmatrix.sync.aligned.m8n8.x2.trans.shared.b16 {%0,%1}, [%2];" \
        : "=r"((r)[0]), "=r"((r)[1]) : "r"(a))
#define LDSM_X1T(r, a) \
    asm volatile("ldmatrix.sync.aligned.m8n8.x1.trans.shared.b16 {%0}, [%1];" \
        : "=r"(r) : "r"(a))
#define MMA16816(c, a, b) \
    asm volatile("mma.sync.aligned.m16n8k16.row.col.f32.f16.f16.f32 " \
        "{%0,%1,%2,%3},{%4,%5,%6,%7},{%8,%9},{%0,%1,%2,%3};" \
        : "+f"((c)[0]), "+f"((c)[1]), "+f"((c)[2]), "+f"((c)[3]) \
        : "r"((a)[0]), "r"((a)[1]), "r"((a)[2]), "r"((a)[3]), "r"((b)[0]), "r"((b)[1]))
#define MMA1688(c, a, b) \
    asm volatile("mma.sync.aligned.m16n8k8.row.col.f32.f16.f16.f32 " \
        "{%0,%1,%2,%3},{%4,%5},{%6},{%0,%1,%2,%3};" \
        : "+f"((c)[0]), "+f"((c)[1]), "+f"((c)[2]), "+f"((c)[3]) \
        : "r"((a)[0]), "r"((a)[1]), "r"(b))

__global__ void zero_kernel() {
    int total = N_NODES * OUT_CH;
    for (int i = blockIdx.x * blockDim.x + threadIdx.x; i < total; i += gridDim.x * blockDim.x) {
        g_agg[i] = 0.0f;
        if (i < N_NODES) g_cnt[i] = 0.0f;
    }
}

// One full 104-col layer from register A-fragments: accout = Hin(frag) @ W + bias.
// kt 0..5 are k16 steps; k8 tail (k=96..103) uses afrag[6][0..1].
__device__ __forceinline__ void layer_frag(
    const uint32_t afrag[7][4],
    const __half* __restrict__ W, int sW,
    const float* __restrict__ bias,
    float accout[13][4], int lane)
{
    const int tig = lane & 3;
    #pragma unroll
    for (int j = 0; j < 13; j++) {
        const int c = j * 8 + 2 * tig;
        accout[j][0] = bias[c]; accout[j][1] = bias[c + 1];
        accout[j][2] = bias[c]; accout[j][3] = bias[c + 1];
    }
    const int brow = lane & 15;
    #pragma unroll
    for (int kt = 0; kt < 6; kt++) {
        const int k0 = kt * 16;
        #pragma unroll
        for (int j = 0; j < 13; j++) {
            uint32_t b[2];
            LDSM_X2T(b, smem_u32(W + (k0 + brow) * sW + j * 8));
            MMA16816(accout[j], afrag[kt], b);
        }
    }
    const int brow8 = lane & 7;
    #pragma unroll
    for (int j = 0; j < 13; j++) {
        uint32_t b0;
        LDSM_X1T(b0, smem_u32(W + (96 + brow8) * sW + j * 8));
        MMA1688(accout[j], afrag[6], b0);
    }
}

// Convert acc[13][4] (f32, +relu) into A fragments for the next layer.
__device__ __forceinline__ void cvt_frag(const float acc[13][4], uint32_t afrag[7][4]) {
    #pragma unroll
    for (int kt = 0; kt < 6; kt++) {
        afrag[kt][0] = pack_relu2(acc[2 * kt][0], acc[2 * kt][1]);
        afrag[kt][1] = pack_relu2(acc[2 * kt][2], acc[2 * kt][3]);
        afrag[kt][2] = pack_relu2(acc[2 * kt + 1][0], acc[2 * kt + 1][1]);
        afrag[kt][3] = pack_relu2(acc[2 * kt + 1][2], acc[2 * kt + 1][3]);
    }
    afrag[6][0] = pack_relu2(acc[12][0], acc[12][1]);
    afrag[6][1] = pack_relu2(acc[12][2], acc[12][3]);
    afrag[6][2] = 0; afrag[6][3] = 0;
}

extern __shared__ char smem[];

__global__ void __launch_bounds__(THREADS, 1)
edge_kernel(const float* __restrict__ x,
            const int* __restrict__ ei,
            const float* __restrict__ ea,
            const float* __restrict__ W1, const float* __restrict__ b1,
            const float* __restrict__ W2, const float* __restrict__ b2,
            const float* __restrict__ W3, const float* __restrict__ b3,
            const float* __restrict__ W4, const float* __restrict__ b4)
{
    const int tid = threadIdx.x;
    const int wid = tid >> 5, lane = tid & 31;
    const int grp = lane >> 2, tig = lane & 3;

    __half* W1h = (__half*)(smem + SM_W1);
    __half* W2h = (__half*)(smem + SM_W2);
    __half* W3h = (__half*)(smem + SM_W3);
    __half* W4h = (__half*)(smem + SM_W4);
    __half* A0h = (__half*)(smem + SM_A0);
    float*  XV  = (float*)(smem + SM_XV);
    float*  B1f = (float*)(smem + SM_B1);
    float*  B2f = (float*)(smem + SM_B2);
    float*  B3f = (float*)(smem + SM_B3);
    float*  B4f = (float*)(smem + SM_B4);

    for (int i = tid; i < W_ZERO_U32; i += THREADS) ((uint32_t*)smem)[i] = 0;
    __syncthreads();
    for (int i = tid; i < 8 * 100; i += THREADS) {
        int k = i / 100, n = i % 100;
        W1h[k * 120 + n] = __float2half(W1[i]);
    }
    for (int i = tid; i < 100 * 100; i += THREADS) {
        int k = i / 100, n = i % 100;
        W2h[k * 120 + n] = __float2half(W2[i]);
        W3h[k * 120 + n] = __float2half(W3[i]);
    }
    for (int i = tid; i < 100 * 256; i += THREADS) {
        int k = i >> 8, n = i & 255;
        W4h[k * 264 + n] = __float2half(W4[i]);
    }
    for (int i = tid; i < 112; i += THREADS) {
        B1f[i] = (i < 100) ? b1[i] : 0.0f;
        B2f[i] = (i < 100) ? b2[i] : 0.0f;
        B3f[i] = (i < 100) ? b3[i] : 0.0f;
    }
    for (int i = tid; i < 256; i += THREADS) B4f[i] = b4[i];
    __syncthreads();

    const int mrow = wid * 16;                 // warp's rows within CTA tile
    __half* A0w = A0h + mrow * 24;
    float*  XVw = XV + mrow * 20;

    // hoisted L1 B fragments (W1 rows 0..7, all 13 n-tiles)
    uint32_t bt1[13];
    {
        const int brow8 = lane & 7;
        #pragma unroll
        for (int j = 0; j < 13; j++)
            LDSM_X1T(bt1[j], smem_u32(W1h + brow8 * 120 + j * 8));
    }

    const int e2 = lane >> 1;                  // staging: edge 0..15
    const int half8 = (lane & 1);              // which 8-col half

    // register prefetch: lane<16 -> src[lane], lane>=16 -> dst[lane-16]; attrs float4
    int pf_id = 0;
    float4 pf_at = make_float4(0.f, 0.f, 0.f, 0.f);
    {
        const int base = blockIdx.x * M_TILE + mrow;
        if (base < N_EDGES) {
            pf_id = ei[(lane < 16 ? 0 : N_EDGES) + base + (lane & 15)];
            pf_at = ((const float4*)ea)[(long)(base + e2) * 2 + half8];
        }
    }

    for (int t = blockIdx.x; t < NT_TILES; t += GRID) {
        const int wbase = t * M_TILE + mrow;
        if (wbase >= N_EDGES) continue;        // stays inactive for all later t

        const int cur_id = pf_id;

        // stage attrs into A0 (this warp's rows only)
        {
            __half2 h0 = __floats2half2_rn(pf_at.x, pf_at.y);
            __half2 h1 = __floats2half2_rn(pf_at.z, pf_at.w);
            __half* p = A0w + e2 * 24 + half8 * 4;
            *(__half2*)p = h0;
            *(__half2*)(p + 2) = h1;
        }
        __syncwarp();

        // x[src] gather (issued early; consumed via XV before L4)
        const int srcn = __shfl_sync(0xffffffffu, cur_id, e2);
        const float4 xa = ((const float4*)x)[(long)srcn * 4 + half8 * 2];
        const float4 xb = ((const float4*)x)[(long)srcn * 4 + half8 * 2 + 1];

        // ---- L1 (K=8) ----
        uint32_t afrag[7][4];
        {
            uint32_t a2[2];
            LDSM_X2(a2, smem_u32(A0w + (lane & 15) * 24));
            float acc[13][4];
            #pragma unroll
            for (int j = 0; j < 13; j++) {
                const int c = j * 8 + 2 * tig;
                acc[j][0] = B1f[c]; acc[j][1] = B1f[c + 1];
                acc[j][2] = B1f[c]; acc[j][3] = B1f[c + 1];
            }
            #pragma unroll
            for (int j = 0; j < 13; j++)
                MMA1688(acc[j], a2, bt1[j]);
            cvt_frag(acc, afrag);
        }

        // prefetch next tile (overlaps L2/L3)
        {
            const int basen = (t + GRID) * M_TILE + mrow;
            if (basen < N_EDGES) {
                pf_id = ei[(lane < 16 ? 0 : N_EDGES) + basen + (lane & 15)];
                pf_at = ((const float4*)ea)[(long)(basen + e2) * 2 + half8];
            }
        }

        // ---- L2 ----
        {
            float acc[13][4];
            layer_frag(afrag, W2h, 120, B2f, acc, lane);
            cvt_frag(acc, afrag);
        }

        // park x into XV (cross-lane use in L4)
        {
            float* p = XVw + e2 * 20 + half8 * 8;
            *(float4*)p = xa;
            *(float4*)(p + 4) = xb;
        }

        // ---- L3 ----
        {
            float acc[13][4];
            layer_frag(afrag, W3h, 120, B3f, acc, lane);
            cvt_frag(acc, afrag);
        }
        __syncwarp();   // XV visible to all lanes

        // ---- L4 in 4 chunks of 8 n-tiles, fused einsum ----
        float msg[2][2][2];
        #pragma unroll
        for (int h = 0; h < 2; h++)
            #pragma unroll
            for (int p = 0; p < 2; p++) { msg[h][p][0] = 0.f; msg[h][p][1] = 0.f; }
        const int brow = lane & 15;
        const int brow8 = lane & 7;
        #pragma unroll
        for (int c = 0; c < 4; c++) {
            float acc4[8][4];
            #pragma unroll
            for (int j = 0; j < 8; j++) {
                const int col = (8 * c + j) * 8 + 2 * tig;
                acc4[j][0] = B4f[col]; acc4[j][1] = B4f[col + 1];
                acc4[j][2] = B4f[col]; acc4[j][3] = B4f[col + 1];
            }
            #pragma unroll
            for (int kt = 0; kt < 6; kt++) {
                const int k0 = kt * 16;
                #pragma unroll
                for (int j = 0; j < 8; j++) {
                    uint32_t b[2];
                    LDSM_X2T(b, smem_u32(W4h + (k0 + brow) * 264 + (8 * c + j) * 8));
                    MMA16816(acc4[j], afrag[kt], b);
                }
            }
            #pragma unroll
            for (int j = 0; j < 8; j++) {
                uint32_t b0;
                LDSM_X1T(b0, smem_u32(W4h + (96 + brow8) * 264 + (8 * c + j) * 8));
                MMA1688(acc4[j], afrag[6], b0);
            }
            // fold einsum for this chunk: i = 4c + (j>>1), o = (j&1)*8 + 2tig (+1)
            float xv0[4], xv1[4];
            #pragma unroll
            for (int ii = 0; ii < 4; ii++) {
                xv0[ii] = XVw[grp * 20 + 4 * c + ii];
                xv1[ii] = XVw[(grp + 8) * 20 + 4 * c + ii];
            }
            #pragma unroll
            for (int j = 0; j < 8; j++) {
                const int par = j & 1, ii = j >> 1;
                msg[0][par][0] += xv0[ii] * acc4[j][0];
                msg[0][par][1] += xv0[ii] * acc4[j][1];
                msg[1][par][0] += xv1[ii] * acc4[j][2];
                msg[1][par][1] += xv1[ii] * acc4[j][3];
            }
        }

        // ---- scatter: direct global REDs (warp-complete msg) ----
        const int dst0 = __shfl_sync(0xffffffffu, cur_id, 16 + grp);
        const int dst8 = __shfl_sync(0xffffffffu, cur_id, 24 + grp);
        {
            float* p0 = g_agg + (long)dst0 * OUT_CH;
            atomicAdd(p0 + 2 * tig,     msg[0][0][0]);
            atomicAdd(p0 + 2 * tig + 1, msg[0][0][1]);
            atomicAdd(p0 + 8 + 2 * tig,     msg[0][1][0]);
            atomicAdd(p0 + 8 + 2 * tig + 1, msg[0][1][1]);
            float* p1 = g_agg + (long)dst8 * OUT_CH;
            atomicAdd(p1 + 2 * tig,     msg[1][0][0]);
            atomicAdd(p1 + 2 * tig + 1, msg[1][0][1]);
            atomicAdd(p1 + 8 + 2 * tig,     msg[1][1][0]);
            atomicAdd(p1 + 8 + 2 * tig + 1, msg[1][1][1]);
        }
        if (lane >= 16) atomicAdd(&g_cnt[cur_id], 1.0f);
        __syncwarp();   // protect A0/XV rows before next iteration's staging
    }
}

__global__ void finalize_kernel(const float* __restrict__ x,
                                const float* __restrict__ root,
                                const float* __restrict__ bias,
                                float* __restrict__ out)
{
    int i = blockIdx.x * blockDim.x + threadIdx.x;
    if (i >= N_NODES * OUT_CH) return;
    int n = i >> 4, o = i & 15;
    float c = fmaxf(g_cnt[n], 1.0f);
    float acc = g_agg[i] / c + bias[o];
    const float* xr = x + (long)n * IN_CH;
    #pragma unroll
    for (int k = 0; k < IN_CH; k++)
        acc += xr[k] * root[k * OUT_CH + o];
    out[i] = acc;
}

extern "C" void kernel_launch(void* const* d_in, const int* in_sizes, int n_in,
                              void* d_out, int out_size) {
    const float* x    = (const float*)d_in[0];
    const int*   ei   = (const int*)d_in[1];
    const float* ea   = (const float*)d_in[2];
    const float* W1   = (const float*)d_in[3];
    const float* b1   = (const float*)d_in[4];
    const float* W2   = (const float*)d_in[5];
    const float* b2   = (const float*)d_in[6];
    const float* W3   = (const float*)d_in[7];
    const float* b3   = (const float*)d_in[8];
    const float* W4   = (const float*)d_in[9];
    const float* b4   = (const float*)d_in[10];
    const float* root = (const float*)d_in[11];
    const float* bias = (const float*)d_in[12];
    float* out = (float*)d_out;

    cudaFuncSetAttribute(edge_kernel, cudaFuncAttributeMaxDynamicSharedMemorySize, SMEM_BYTES);

    zero_kernel<<<1024, 256>>>();
    edge_kernel<<<GRID, THREADS, SMEM_BYTES>>>(x, ei, ea, W1, b1, W2, b2, W3, b3, W4, b4);
    finalize_kernel<<<(N_NODES * OUT_CH + 255) / 256, 256>>>(x, root, bias, out);
}

// round 16
// speedup vs baseline: 1.2053x; 1.2053x over previous
#include <cuda_runtime.h>
#include <cuda_fp16.h>
#include <cstdint>

#define N_NODES 50000
#define N_EDGES 800000
#define IN_CH 16
#define OUT_CH 16
#define M_TILE 192
#define NT_TILES ((N_EDGES + M_TILE - 1) / M_TILE)   // 4167
#define THREADS 384
#define GRID 152

// ---- smem byte offsets ----
#define SM_W1   0        // [16][120] f16   = 3840
#define SM_W2   3840     // [112][120] f16  = 26880
#define SM_W3   30720    // [112][120] f16  = 26880
#define SM_W4   57600    // [112][264] f16  = 59136
#define SM_A0   116736   // [192][24] f16   = 9216
#define SM_XV   125952   // [192][20] f32   = 15360
#define SM_B1   141312   // [112] f32
#define SM_B2   141760
#define SM_B3   142208
#define SM_B4   142656   // [256] f32
#define SMEM_BYTES 143680
#define W_ZERO_U32 (116736 / 4)

__device__ float g_agg[N_NODES * OUT_CH];
__device__ float g_cnt[N_NODES];

__device__ __forceinline__ uint32_t smem_u32(const void* p) {
    uint32_t a;
    asm("{ .reg .u64 t; cvta.to.shared.u64 t, %1; cvt.u32.u64 %0, t; }" : "=r"(a) : "l"(p));
    return a;
}
__device__ __forceinline__ uint32_t pack_relu2(float a, float b) {
    __half2 h = __floats2half2_rn(fmaxf(a, 0.f), fmaxf(b, 0.f));
    return *(uint32_t*)&h;
}

#define LDSM_X2(r, a) \
    asm volatile("ldmatrix.sync.aligned.m8n8.x2.shared.b16 {%0,%1}, [%2];" \
        : "=r"((r)[0]), "=r"((r)[1]) : "r"(a))
#define LDSM_X4T(r, a) \
    asm volatile("ldmatrix.sync.aligned.m8n8.x4.trans.shared.b16 {%0,%1,%2,%3}, [%4];" \
        : "=r"((r)[0]), "=r"((r)[1]), "=r"((r)[2]), "=r"((r)[3]) : "r"(a))
#define LDSM_X2T(r, a) \
    asm volatile("ldmatrix.sync.aligned.m8n8.x2.trans.shared.b16 {%0,%1}, [%2];" \
        : "=r"((r)[0]), "=r"((r)[1]) : "r"(a))
#define LDSM_X1T(r, a) \
    asm volatile("ldmatrix.sync.aligned.m8n8.x1.trans.shared.b16 {%0}, [%1];" \
        : "=r"(r) : "r"(a))
#define MMA16816(c, a, b0, b1) \
    asm volatile("mma.sync.aligned.m16n8k16.row.col.f32.f16.f16.f32 " \
        "{%0,%1,%2,%3},{%4,%5,%6,%7},{%8,%9},{%0,%1,%2,%3};" \
        : "+f"((c)[0]), "+f"((c)[1]), "+f"((c)[2]), "+f"((c)[3]) \
        : "r"((a)[0]), "r"((a)[1]), "r"((a)[2]), "r"((a)[3]), "r"(b0), "r"(b1))
#define MMA1688(c, a, b) \
    asm volatile("mma.sync.aligned.m16n8k8.row.col.f32.f16.f16.f32 " \
        "{%0,%1,%2,%3},{%4,%5},{%6},{%0,%1,%2,%3};" \
        : "+f"((c)[0]), "+f"((c)[1]), "+f"((c)[2]), "+f"((c)[3]) \
        : "r"((a)[0]), "r"((a)[1]), "r"(b))

__global__ void zero_kernel() {
    int total = N_NODES * OUT_CH;
    for (int i = blockIdx.x * blockDim.x + threadIdx.x; i < total; i += gridDim.x * blockDim.x) {
        g_agg[i] = 0.0f;
        if (i < N_NODES) g_cnt[i] = 0.0f;
    }
}

// One full 104-col layer from register A-fragments: accout = Hin(frag) @ W + bias.
__device__ __forceinline__ void layer_frag(
    const uint32_t afrag[7][4],
    const __half* __restrict__ W, int sW,
    const float* __restrict__ bias,
    float accout[13][4], int lane)
{
    const int tig = lane & 3;
    #pragma unroll
    for (int j = 0; j < 13; j++) {
        const int c = j * 8 + 2 * tig;
        accout[j][0] = bias[c]; accout[j][1] = bias[c + 1];
        accout[j][2] = bias[c]; accout[j][3] = bias[c + 1];
    }
    const int brow = lane & 15;
    #pragma unroll
    for (int kt = 0; kt < 6; kt++) {
        const int k0 = kt * 16;
        #pragma unroll
        for (int j = 0; j < 13; j++) {
            uint32_t b[2];
            LDSM_X2T(b, smem_u32(W + (k0 + brow) * sW + j * 8));
            MMA16816(accout[j], afrag[kt], b[0], b[1]);
        }
    }
    const int brow8 = lane & 7;
    #pragma unroll
    for (int j = 0; j < 13; j++) {
        uint32_t b0;
        LDSM_X1T(b0, smem_u32(W + (96 + brow8) * sW + j * 8));
        MMA1688(accout[j], afrag[6], b0);
    }
}

// Convert acc[13][4] (f32, +relu) into A fragments for the next layer.
__device__ __forceinline__ void cvt_frag(const float acc[13][4], uint32_t afrag[7][4]) {
    #pragma unroll
    for (int kt = 0; kt < 6; kt++) {
        afrag[kt][0] = pack_relu2(acc[2 * kt][0], acc[2 * kt][1]);
        afrag[kt][1] = pack_relu2(acc[2 * kt][2], acc[2 * kt][3]);
        afrag[kt][2] = pack_relu2(acc[2 * kt + 1][0], acc[2 * kt + 1][1]);
        afrag[kt][3] = pack_relu2(acc[2 * kt + 1][2], acc[2 * kt + 1][3]);
    }
    afrag[6][0] = pack_relu2(acc[12][0], acc[12][1]);
    afrag[6][1] = pack_relu2(acc[12][2], acc[12][3]);
    afrag[6][2] = 0; afrag[6][3] = 0;
}

extern __shared__ char smem[];

__global__ void __launch_bounds__(THREADS, 1)
edge_kernel(const float* __restrict__ x,
            const int* __restrict__ ei,
            const float* __restrict__ ea,
            const float* __restrict__ W1, const float* __restrict__ b1,
            const float* __restrict__ W2, const float* __restrict__ b2,
            const float* __restrict__ W3, const float* __restrict__ b3,
            const float* __restrict__ W4, const float* __restrict__ b4)
{
    const int tid = threadIdx.x;
    const int wid = tid >> 5, lane = tid & 31;
    const int grp = lane >> 2, tig = lane & 3;

    __half* W1h = (__half*)(smem + SM_W1);
    __half* W2h = (__half*)(smem + SM_W2);
    __half* W3h = (__half*)(smem + SM_W3);
    __half* W4h = (__half*)(smem + SM_W4);
    __half* A0h = (__half*)(smem + SM_A0);
    float*  XV  = (float*)(smem + SM_XV);
    float*  B1f = (float*)(smem + SM_B1);
    float*  B2f = (float*)(smem + SM_B2);
    float*  B3f = (float*)(smem + SM_B3);
    float*  B4f = (float*)(smem + SM_B4);

    for (int i = tid; i < W_ZERO_U32; i += THREADS) ((uint32_t*)smem)[i] = 0;
    __syncthreads();
    for (int i = tid; i < 8 * 100; i += THREADS) {
        int k = i / 100, n = i % 100;
        W1h[k * 120 + n] = __float2half(W1[i]);
    }
    for (int i = tid; i < 100 * 100; i += THREADS) {
        int k = i / 100, n = i % 100;
        W2h[k * 120 + n] = __float2half(W2[i]);
        W3h[k * 120 + n] = __float2half(W3[i]);
    }
    for (int i = tid; i < 100 * 256; i += THREADS) {
        int k = i >> 8, n = i & 255;
        W4h[k * 264 + n] = __float2half(W4[i]);
    }
    for (int i = tid; i < 112; i += THREADS) {
        B1f[i] = (i < 100) ? b1[i] : 0.0f;
        B2f[i] = (i < 100) ? b2[i] : 0.0f;
        B3f[i] = (i < 100) ? b3[i] : 0.0f;
    }
    for (int i = tid; i < 256; i += THREADS) B4f[i] = b4[i];
    __syncthreads();

    const int mrow = wid * 16;                 // warp's rows within CTA tile
    __half* A0w = A0h + mrow * 24;
    float*  XVw = XV + mrow * 20;

    // hoisted L1 B fragments (W1 rows 0..7, all 13 n-tiles)
    uint32_t bt1[13];
    {
        const int brow8 = lane & 7;
        #pragma unroll
        for (int j = 0; j < 13; j++)
            LDSM_X1T(bt1[j], smem_u32(W1h + brow8 * 120 + j * 8));
    }

    const int e2 = lane >> 1;                  // staging: edge 0..15
    const int half8 = (lane & 1);              // which 8-col half

    int pf_id = 0;
    float4 pf_at = make_float4(0.f, 0.f, 0.f, 0.f);
    {
        const int base = blockIdx.x * M_TILE + mrow;
        if (base < N_EDGES) {
            pf_id = ei[(lane < 16 ? 0 : N_EDGES) + base + (lane & 15)];
            pf_at = ((const float4*)ea)[(long)(base + e2) * 2 + half8];
        }
    }

    for (int t = blockIdx.x; t < NT_TILES; t += GRID) {
        const int wbase = t * M_TILE + mrow;
        if (wbase >= N_EDGES) continue;

        const int cur_id = pf_id;

        // stage attrs into A0 (this warp's rows only)
        {
            __half2 h0 = __floats2half2_rn(pf_at.x, pf_at.y);
            __half2 h1 = __floats2half2_rn(pf_at.z, pf_at.w);
            __half* p = A0w + e2 * 24 + half8 * 4;
            *(__half2*)p = h0;
            *(__half2*)(p + 2) = h1;
        }
        __syncwarp();

        // x[src] gather (issued early; consumed via XV before L4)
        const int srcn = __shfl_sync(0xffffffffu, cur_id, e2);
        const float4 xa = ((const float4*)x)[(long)srcn * 4 + half8 * 2];
        const float4 xb = ((const float4*)x)[(long)srcn * 4 + half8 * 2 + 1];

        // ---- L1 (K=8) ----
        uint32_t afrag[7][4];
        {
            uint32_t a2[2];
            LDSM_X2(a2, smem_u32(A0w + (lane & 15) * 24));
            float acc[13][4];
            #pragma unroll
            for (int j = 0; j < 13; j++) {
                const int c = j * 8 + 2 * tig;
                acc[j][0] = B1f[c]; acc[j][1] = B1f[c + 1];
                acc[j][2] = B1f[c]; acc[j][3] = B1f[c + 1];
            }
            #pragma unroll
            for (int j = 0; j < 13; j++)
                MMA1688(acc[j], a2, bt1[j]);
            cvt_frag(acc, afrag);
        }

        // prefetch next tile (overlaps L2/L3)
        {
            const int basen = (t + GRID) * M_TILE + mrow;
            if (basen < N_EDGES) {
                pf_id = ei[(lane < 16 ? 0 : N_EDGES) + basen + (lane & 15)];
                pf_at = ((const float4*)ea)[(long)(basen + e2) * 2 + half8];
            }
        }

        // ---- L2 ----
        {
            float acc[13][4];
            layer_frag(afrag, W2h, 120, B2f, acc, lane);
            cvt_frag(acc, afrag);
        }

        // park x into XV (cross-lane use in L4)
        {
            float* p = XVw + e2 * 20 + half8 * 8;
            *(float4*)p = xa;
            *(float4*)(p + 4) = xb;
        }

        // ---- L3 ----
        {
            float acc[13][4];
            layer_frag(afrag, W3h, 120, B3f, acc, lane);
            cvt_frag(acc, afrag);
        }
        __syncwarp();   // XV visible to all lanes

        // ---- L4 in 4 chunks of 8 n-tiles (4 n-pairs via x4.trans), fused einsum ----
        float msg[2][2][2];
        #pragma unroll
        for (int h = 0; h < 2; h++)
            #pragma unroll
            for (int p = 0; p < 2; p++) { msg[h][p][0] = 0.f; msg[h][p][1] = 0.f; }
        const int brow = lane & 15;
        const int bcol16 = (lane >> 4) * 8;
        const int brow8 = lane & 7;
        const int bcol8 = ((lane >> 3) & 1) * 8;
        #pragma unroll
        for (int c = 0; c < 4; c++) {
            float acc4[8][4];
            #pragma unroll
            for (int j = 0; j < 8; j++) {
                const int col = (8 * c + j) * 8 + 2 * tig;
                acc4[j][0] = B4f[col]; acc4[j][1] = B4f[col + 1];
                acc4[j][2] = B4f[col]; acc4[j][3] = B4f[col + 1];
            }
            #pragma unroll
            for (int kt = 0; kt < 6; kt++) {
                const int k0 = kt * 16;
                #pragma unroll
                for (int jp = 0; jp < 4; jp++) {
                    uint32_t b[4];
                    LDSM_X4T(b, smem_u32(W4h + (k0 + brow) * 264 + (8 * c + 2 * jp) * 8 + bcol16));
                    MMA16816(acc4[2 * jp], afrag[kt], b[0], b[1]);
                    MMA16816(acc4[2 * jp + 1], afrag[kt], b[2], b[3]);
                }
            }
            #pragma unroll
            for (int jp = 0; jp < 4; jp++) {
                uint32_t b[2];
                LDSM_X2T(b, smem_u32(W4h + (96 + brow8) * 264 + (8 * c + 2 * jp) * 8 + bcol8));
                MMA1688(acc4[2 * jp], afrag[6], b[0]);
                MMA1688(acc4[2 * jp + 1], afrag[6], b[1]);
            }
            // fold einsum for this chunk: i = 4c + (j>>1), o = (j&1)*8 + 2tig (+1)
            float xv0[4], xv1[4];
            #pragma unroll
            for (int ii = 0; ii < 4; ii++) {
                xv0[ii] = XVw[grp * 20 + 4 * c + ii];
                xv1[ii] = XVw[(grp + 8) * 20 + 4 * c + ii];
            }
            #pragma unroll
            for (int j = 0; j < 8; j++) {
                const int par = j & 1, ii = j >> 1;
                msg[0][par][0] += xv0[ii] * acc4[j][0];
                msg[0][par][1] += xv0[ii] * acc4[j][1];
                msg[1][par][0] += xv1[ii] * acc4[j][2];
                msg[1][par][1] += xv1[ii] * acc4[j][3];
            }
        }

        // ---- scatter: direct global REDs (warp-complete msg) ----
        const int dst0 = __shfl_sync(0xffffffffu, cur_id, 16 + grp);
        const int dst8 = __shfl_sync(0xffffffffu, cur_id, 24 + grp);
        {
            float* p0 = g_agg + (long)dst0 * OUT_CH;
            atomicAdd(p0 + 2 * tig,     msg[0][0][0]);
            atomicAdd(p0 + 2 * tig + 1, msg[0][0][1]);
            atomicAdd(p0 + 8 + 2 * tig,     msg[0][1][0]);
            atomicAdd(p0 + 8 + 2 * tig + 1, msg[0][1][1]);
            float* p1 = g_agg + (long)dst8 * OUT_CH;
            atomicAdd(p1 + 2 * tig,     msg[1][0][0]);
            atomicAdd(p1 + 2 * tig + 1, msg[1][0][1]);
            atomicAdd(p1 + 8 + 2 * tig,     msg[1][1][0]);
            atomicAdd(p1 + 8 + 2 * tig + 1, msg[1][1][1]);
        }
        if (lane >= 16) atomicAdd(&g_cnt[cur_id], 1.0f);
        __syncwarp();   // protect A0/XV rows before next iteration's staging
    }
}

__global__ void finalize_kernel(const float* __restrict__ x,
                                const float* __restrict__ root,
                                const float* __restrict__ bias,
                                float* __restrict__ out)
{
    int i = blockIdx.x * blockDim.x + threadIdx.x;      // node*4 + quarter
    if (i >= N_NODES * 4) return;
    int n = i >> 2, qo = (i & 3) * 4;
    float c = fmaxf(g_cnt[n], 1.0f);
    float4 agg = ((const float4*)g_agg)[i];
    float4 bb = *(const float4*)&bias[qo];
    float4 acc = make_float4(agg.x / c + bb.x, agg.y / c + bb.y,
                             agg.z / c + bb.z, agg.w / c + bb.w);
    const float* xr = x + (long)n * IN_CH;
    #pragma unroll
    for (int k = 0; k < IN_CH; k++) {
        float xk = xr[k];
        float4 r = *(const float4*)&root[k * OUT_CH + qo];
        acc.x += xk * r.x; acc.y += xk * r.y;
        acc.z += xk * r.z; acc.w += xk * r.w;
    }
    ((float4*)out)[i] = acc;
}

extern "C" void kernel_launch(void* const* d_in, const int* in_sizes, int n_in,
                              void* d_out, int out_size) {
    const float* x    = (const float*)d_in[0];
    const int*   ei   = (const int*)d_in[1];
    const float* ea   = (const float*)d_in[2];
    const float* W1   = (const float*)d_in[3];
    const float* b1   = (const float*)d_in[4];
    const float* W2   = (const float*)d_in[5];
    const float* b2   = (const float*)d_in[6];
    const float* W3   = (const float*)d_in[7];
    const float* b3   = (const float*)d_in[8];
    const float* W4   = (const float*)d_in[9];
    const float* b4   = (const float*)d_in[10];
    const float* root = (const float*)d_in[11];
    const float* bias = (const float*)d_in[12];
    float* out = (float*)d_out;

    cudaFuncSetAttribute(edge_kernel, cudaFuncAttributeMaxDynamicSharedMemorySize, SMEM_BYTES);

    zero_kernel<<<1024, 256>>>();
    edge_kernel<<<GRID, THREADS, SMEM_BYTES>>>(x, ei, ea, W1, b1, W2, b2, W3, b3, W4, b4);
    finalize_kernel<<<(N_NODES * 4 + 255) / 256, 256>>>(x, root, bias, out);
}

// round 17
// speedup vs baseline: 1.2287x; 1.0195x over previous
#include <cuda_runtime.h>
#include <cuda_fp16.h>
#include <cstdint>

#define N_NODES 50000
#define N_EDGES 800000
#define IN_CH 16
#define OUT_CH 16
#define M_TILE 192
#define NT_TILES ((N_EDGES + M_TILE - 1) / M_TILE)   // 4167
#define THREADS 384
#define GRID 152

// ---- smem byte offsets ----
#define SM_W1   0        // [16][120] f16   = 3840
#define SM_W2   3840     // [112][120] f16  = 26880
#define SM_W3   30720    // [112][120] f16  = 26880
#define SM_W4   57600    // [112][264] f16  = 59136
#define SM_A0   116736   // [192][24] f16   = 9216
#define SM_XV   125952   // [192][20] f32   = 15360
#define SM_B1   141312   // [112] f32
#define SM_B2   141760
#define SM_B3   142208
#define SM_B4   142656   // [256] f32
#define SMEM_BYTES 143680
#define W_ZERO_U32 (116736 / 4)

__device__ float g_agg[N_NODES * OUT_CH];
__device__ float g_cnt[N_NODES];

__device__ __forceinline__ uint32_t smem_u32(const void* p) {
    uint32_t a;
    asm("{ .reg .u64 t; cvta.to.shared.u64 t, %1; cvt.u32.u64 %0, t; }" : "=r"(a) : "l"(p));
    return a;
}
__device__ __forceinline__ uint32_t pack_relu2(float a, float b) {
    __half2 h = __floats2half2_rn(fmaxf(a, 0.f), fmaxf(b, 0.f));
    return *(uint32_t*)&h;
}

#define LDSM_X2(r, a) \
    asm volatile("ldmatrix.sync.aligned.m8n8.x2.shared.b16 {%0,%1}, [%2];" \
        : "=r"((r)[0]), "=r"((r)[1]) : "r"(a))
#define LDSM_X4T(r, a) \
    asm volatile("ldmatrix.sync.aligned.m8n8.x4.trans.shared.b16 {%0,%1,%2,%3}, [%4];" \
        : "=r"((r)[0]), "=r"((r)[1]), "=r"((r)[2]), "=r"((r)[3]) : "r"(a))
#define LDSM_X2T(r, a) \
    asm volatile("ldmatrix.sync.aligned.m8n8.x2.trans.shared.b16 {%0,%1}, [%2];" \
        : "=r"((r)[0]), "=r"((r)[1]) : "r"(a))
#define LDSM_X1T(r, a) \
    asm volatile("ldmatrix.sync.aligned.m8n8.x1.trans.shared.b16 {%0}, [%1];" \
        : "=r"(r) : "r"(a))
#define MMA16816(c, a, b0, b1) \
    asm volatile("mma.sync.aligned.m16n8k16.row.col.f32.f16.f16.f32 " \
        "{%0,%1,%2,%3},{%4,%5,%6,%7},{%8,%9},{%0,%1,%2,%3};" \
        : "+f"((c)[0]), "+f"((c)[1]), "+f"((c)[2]), "+f"((c)[3]) \
        : "r"((a)[0]), "r"((a)[1]), "r"((a)[2]), "r"((a)[3]), "r"(b0), "r"(b1))
#define MMA1688(c, a, b) \
    asm volatile("mma.sync.aligned.m16n8k8.row.col.f32.f16.f16.f32 " \
        "{%0,%1,%2,%3},{%4,%5},{%6},{%0,%1,%2,%3};" \
        : "+f"((c)[0]), "+f"((c)[1]), "+f"((c)[2]), "+f"((c)[3]) \
        : "r"((a)[0]), "r"((a)[1]), "r"(b))

__global__ void zero_kernel() {
    int total = N_NODES * OUT_CH;
    for (int i = blockIdx.x * blockDim.x + threadIdx.x; i < total; i += gridDim.x * blockDim.x) {
        g_agg[i] = 0.0f;
        if (i < N_NODES) g_cnt[i] = 0.0f;
    }
}

// One full 104-col layer from register A-fragments: accout = Hin(frag) @ W + bias.
// B fetched in n-pairs via x4.trans (6 pairs + 1 odd n-tile).
__device__ __forceinline__ void layer_frag(
    const uint32_t afrag[7][4],
    const __half* __restrict__ W, int sW,
    const float* __restrict__ bias,
    float accout[13][4], int lane)
{
    const int tig = lane & 3;
    #pragma unroll
    for (int j = 0; j < 13; j++) {
        const int c = j * 8 + 2 * tig;
        accout[j][0] = bias[c]; accout[j][1] = bias[c + 1];
        accout[j][2] = bias[c]; accout[j][3] = bias[c + 1];
    }
    const int brow = lane & 15;
    const int bcol16 = (lane >> 4) * 8;
    #pragma unroll
    for (int kt = 0; kt < 6; kt++) {
        const int k0 = kt * 16;
        #pragma unroll
        for (int jp = 0; jp < 6; jp++) {
            uint32_t b[4];
            LDSM_X4T(b, smem_u32(W + (k0 + brow) * sW + jp * 16 + bcol16));
            MMA16816(accout[2 * jp], afrag[kt], b[0], b[1]);
            MMA16816(accout[2 * jp + 1], afrag[kt], b[2], b[3]);
        }
        {   // odd n-tile 12
            uint32_t b[2];
            LDSM_X2T(b, smem_u32(W + (k0 + brow) * sW + 96));
            MMA16816(accout[12], afrag[kt], b[0], b[1]);
        }
    }
    const int brow8 = lane & 7;
    const int bcol8 = ((lane >> 3) & 1) * 8;
    #pragma unroll
    for (int jp = 0; jp < 6; jp++) {
        uint32_t b[2];
        LDSM_X2T(b, smem_u32(W + (96 + brow8) * sW + jp * 16 + bcol8));
        MMA1688(accout[2 * jp], afrag[6], b[0]);
        MMA1688(accout[2 * jp + 1], afrag[6], b[1]);
    }
    {
        uint32_t b0;
        LDSM_X1T(b0, smem_u32(W + (96 + brow8) * sW + 96));
        MMA1688(accout[12], afrag[6], b0);
    }
}

// Convert acc[13][4] (f32, +relu) into A fragments for the next layer.
__device__ __forceinline__ void cvt_frag(const float acc[13][4], uint32_t afrag[7][4]) {
    #pragma unroll
    for (int kt = 0; kt < 6; kt++) {
        afrag[kt][0] = pack_relu2(acc[2 * kt][0], acc[2 * kt][1]);
        afrag[kt][1] = pack_relu2(acc[2 * kt][2], acc[2 * kt][3]);
        afrag[kt][2] = pack_relu2(acc[2 * kt + 1][0], acc[2 * kt + 1][1]);
        afrag[kt][3] = pack_relu2(acc[2 * kt + 1][2], acc[2 * kt + 1][3]);
    }
    afrag[6][0] = pack_relu2(acc[12][0], acc[12][1]);
    afrag[6][1] = pack_relu2(acc[12][2], acc[12][3]);
    afrag[6][2] = 0; afrag[6][3] = 0;
}

extern __shared__ char smem[];

__global__ void __launch_bounds__(THREADS, 1)
edge_kernel(const float* __restrict__ x,
            const int* __restrict__ ei,
            const float* __restrict__ ea,
            const float* __restrict__ W1, const float* __restrict__ b1,
            const float* __restrict__ W2, const float* __restrict__ b2,
            const float* __restrict__ W3, const float* __restrict__ b3,
            const float* __restrict__ W4, const float* __restrict__ b4)
{
    const int tid = threadIdx.x;
    const int wid = tid >> 5, lane = tid & 31;
    const int grp = lane >> 2, tig = lane & 3;

    __half* W1h = (__half*)(smem + SM_W1);
    __half* W2h = (__half*)(smem + SM_W2);
    __half* W3h = (__half*)(smem + SM_W3);
    __half* W4h = (__half*)(smem + SM_W4);
    __half* A0h = (__half*)(smem + SM_A0);
    float*  XV  = (float*)(smem + SM_XV);
    float*  B1f = (float*)(smem + SM_B1);
    float*  B2f = (float*)(smem + SM_B2);
    float*  B3f = (float*)(smem + SM_B3);
    float*  B4f = (float*)(smem + SM_B4);

    for (int i = tid; i < W_ZERO_U32; i += THREADS) ((uint32_t*)smem)[i] = 0;
    __syncthreads();
    for (int i = tid; i < 8 * 100; i += THREADS) {
        int k = i / 100, n = i % 100;
        W1h[k * 120 + n] = __float2half(W1[i]);
    }
    for (int i = tid; i < 100 * 100; i += THREADS) {
        int k = i / 100, n = i % 100;
        W2h[k * 120 + n] = __float2half(W2[i]);
        W3h[k * 120 + n] = __float2half(W3[i]);
    }
    for (int i = tid; i < 100 * 256; i += THREADS) {
        int k = i >> 8, n = i & 255;
        W4h[k * 264 + n] = __float2half(W4[i]);
    }
    for (int i = tid; i < 112; i += THREADS) {
        B1f[i] = (i < 100) ? b1[i] : 0.0f;
        B2f[i] = (i < 100) ? b2[i] : 0.0f;
        B3f[i] = (i < 100) ? b3[i] : 0.0f;
    }
    for (int i = tid; i < 256; i += THREADS) B4f[i] = b4[i];
    __syncthreads();

    const int mrow = wid * 16;                 // warp's rows within CTA tile
    __half* A0w = A0h + mrow * 24;
    float*  XVw = XV + mrow * 20;

    // hoisted L1 B fragments (W1 rows 0..7, all 13 n-tiles)
    uint32_t bt1[13];
    {
        const int brow8 = lane & 7;
        #pragma unroll
        for (int j = 0; j < 13; j++)
            LDSM_X1T(bt1[j], smem_u32(W1h + brow8 * 120 + j * 8));
    }

    const int e2 = lane >> 1;                  // staging: edge 0..15
    const int half8 = (lane & 1);              // which 8-col half

    int pf_id = 0;
    float4 pf_at = make_float4(0.f, 0.f, 0.f, 0.f);
    {
        const int base = blockIdx.x * M_TILE + mrow;
        if (base < N_EDGES) {
            pf_id = ei[(lane < 16 ? 0 : N_EDGES) + base + (lane & 15)];
            pf_at = ((const float4*)ea)[(long)(base + e2) * 2 + half8];
        }
    }

    for (int t = blockIdx.x; t < NT_TILES; t += GRID) {
        const int wbase = t * M_TILE + mrow;
        if (wbase >= N_EDGES) continue;

        const int cur_id = pf_id;

        // stage attrs into A0 (this warp's rows only)
        {
            __half2 h0 = __floats2half2_rn(pf_at.x, pf_at.y);
            __half2 h1 = __floats2half2_rn(pf_at.z, pf_at.w);
            __half* p = A0w + e2 * 24 + half8 * 4;
            *(__half2*)p = h0;
            *(__half2*)(p + 2) = h1;
        }
        __syncwarp();

        // x[src] gather (issued early; consumed via XV before L4)
        const int srcn = __shfl_sync(0xffffffffu, cur_id, e2);
        const float4 xa = ((const float4*)x)[(long)srcn * 4 + half8 * 2];
        const float4 xb = ((const float4*)x)[(long)srcn * 4 + half8 * 2 + 1];

        // ---- L1 (K=8) ----
        uint32_t afrag[7][4];
        {
            uint32_t a2[2];
            LDSM_X2(a2, smem_u32(A0w + (lane & 15) * 24));
            float acc[13][4];
            #pragma unroll
            for (int j = 0; j < 13; j++) {
                const int c = j * 8 + 2 * tig;
                acc[j][0] = B1f[c]; acc[j][1] = B1f[c + 1];
                acc[j][2] = B1f[c]; acc[j][3] = B1f[c + 1];
            }
            #pragma unroll
            for (int j = 0; j < 13; j++)
                MMA1688(acc[j], a2, bt1[j]);
            cvt_frag(acc, afrag);
        }

        // prefetch next tile (overlaps L2/L3)
        {
            const int basen = (t + GRID) * M_TILE + mrow;
            if (basen < N_EDGES) {
                pf_id = ei[(lane < 16 ? 0 : N_EDGES) + basen + (lane & 15)];
                pf_at = ((const float4*)ea)[(long)(basen + e2) * 2 + half8];
            }
        }

        // ---- L2 ----
        {
            float acc[13][4];
            layer_frag(afrag, W2h, 120, B2f, acc, lane);
            cvt_frag(acc, afrag);
        }

        // park x into XV (cross-lane use in L4)
        {
            float* p = XVw + e2 * 20 + half8 * 8;
            *(float4*)p = xa;
            *(float4*)(p + 4) = xb;
        }

        // ---- L3 ----
        {
            float acc[13][4];
            layer_frag(afrag, W3h, 120, B3f, acc, lane);
            cvt_frag(acc, afrag);
        }
        __syncwarp();   // XV visible to all lanes

        // ---- L4 in 4 chunks of 8 n-tiles (4 n-pairs via x4.trans), fused einsum ----
        float msg[2][2][2];
        #pragma unroll
        for (int h = 0; h < 2; h++)
            #pragma unroll
            for (int p = 0; p < 2; p++) { msg[h][p][0] = 0.f; msg[h][p][1] = 0.f; }
        const int brow = lane & 15;
        const int bcol16 = (lane >> 4) * 8;
        const int brow8 = lane & 7;
        const int bcol8 = ((lane >> 3) & 1) * 8;
        #pragma unroll
        for (int c = 0; c < 4; c++) {
            float acc4[8][4];
            #pragma unroll
            for (int j = 0; j < 8; j++) {
                const int col = (8 * c + j) * 8 + 2 * tig;
                acc4[j][0] = B4f[col]; acc4[j][1] = B4f[col + 1];
                acc4[j][2] = B4f[col]; acc4[j][3] = B4f[col + 1];
            }
            #pragma unroll
            for (int kt = 0; kt < 6; kt++) {
                const int k0 = kt * 16;
                #pragma unroll
                for (int jp = 0; jp < 4; jp++) {
                    uint32_t b[4];
                    LDSM_X4T(b, smem_u32(W4h + (k0 + brow) * 264 + (8 * c + 2 * jp) * 8 + bcol16));
                    MMA16816(acc4[2 * jp], afrag[kt], b[0], b[1]);
                    MMA16816(acc4[2 * jp + 1], afrag[kt], b[2], b[3]);
                }
            }
            #pragma unroll
            for (int jp = 0; jp < 4; jp++) {
                uint32_t b[2];
                LDSM_X2T(b, smem_u32(W4h + (96 + brow8) * 264 + (8 * c + 2 * jp) * 8 + bcol8));
                MMA1688(acc4[2 * jp], afrag[6], b[0]);
                MMA1688(acc4[2 * jp + 1], afrag[6], b[1]);
            }
            // fold einsum for this chunk: i = 4c + (j>>1), o = (j&1)*8 + 2tig (+1)
            float xv0[4], xv1[4];
            #pragma unroll
            for (int ii = 0; ii < 4; ii++) {
                xv0[ii] = XVw[grp * 20 + 4 * c + ii];
                xv1[ii] = XVw[(grp + 8) * 20 + 4 * c + ii];
            }
            #pragma unroll
            for (int j = 0; j < 8; j++) {
                const int par = j & 1, ii = j >> 1;
                msg[0][par][0] += xv0[ii] * acc4[j][0];
                msg[0][par][1] += xv0[ii] * acc4[j][1];
                msg[1][par][0] += xv1[ii] * acc4[j][2];
                msg[1][par][1] += xv1[ii] * acc4[j][3];
            }
        }

        // ---- scatter: direct global REDs (warp-complete msg) ----
        const int dst0 = __shfl_sync(0xffffffffu, cur_id, 16 + grp);
        const int dst8 = __shfl_sync(0xffffffffu, cur_id, 24 + grp);
        {
            float* p0 = g_agg + (long)dst0 * OUT_CH;
            atomicAdd(p0 + 2 * tig,     msg[0][0][0]);
            atomicAdd(p0 + 2 * tig + 1, msg[0][0][1]);
            atomicAdd(p0 + 8 + 2 * tig,     msg[0][1][0]);
            atomicAdd(p0 + 8 + 2 * tig + 1, msg[0][1][1]);
            float* p1 = g_agg + (long)dst8 * OUT_CH;
            atomicAdd(p1 + 2 * tig,     msg[1][0][0]);
            atomicAdd(p1 + 2 * tig + 1, msg[1][0][1]);
            atomicAdd(p1 + 8 + 2 * tig,     msg[1][1][0]);
            atomicAdd(p1 + 8 + 2 * tig + 1, msg[1][1][1]);
        }
        if (lane >= 16) atomicAdd(&g_cnt[cur_id], 1.0f);
        __syncwarp();   // protect A0/XV rows before next iteration's staging
    }
}

__global__ void finalize_kernel(const float* __restrict__ x,
                                const float* __restrict__ root,
                                const float* __restrict__ bias,
                                float* __restrict__ out)
{
    int i = blockIdx.x * blockDim.x + threadIdx.x;      // node*4 + quarter
    if (i >= N_NODES * 4) return;
    int n = i >> 2, qo = (i & 3) * 4;
    float c = fmaxf(g_cnt[n], 1.0f);
    float4 agg = ((const float4*)g_agg)[i];
    float4 bb = *(const float4*)&bias[qo];
    float4 acc = make_float4(agg.x / c + bb.x, agg.y / c + bb.y,
                             agg.z / c + bb.z, agg.w / c + bb.w);
    const float* xr = x + (long)n * IN_CH;
    #pragma unroll
    for (int k = 0; k < IN_CH; k++) {
        float xk = xr[k];
        float4 r = *(const float4*)&root[k * OUT_CH + qo];
        acc.x += xk * r.x; acc.y += xk * r.y;
        acc.z += xk * r.z; acc.w += xk * r.w;
    }
    ((float4*)out)[i] = acc;
}

extern "C" void kernel_launch(void* const* d_in, const int* in_sizes, int n_in,
                              void* d_out, int out_size) {
    const float* x    = (const float*)d_in[0];
    const int*   ei   = (const int*)d_in[1];
    const float* ea   = (const float*)d_in[2];
    const float* W1   = (const float*)d_in[3];
    const float* b1   = (const float*)d_in[4];
    const float* W2   = (const float*)d_in[5];
    const float* b2   = (const float*)d_in[6];
    const float* W3   = (const float*)d_in[7];
    const float* b3   = (const float*)d_in[8];
    const float* W4   = (const float*)d_in[9];
    const float* b4   = (const float*)d_in[10];
    const float* root = (const float*)d_in[11];
    const float* bias = (const float*)d_in[12];
    float* out = (float*)d_out;

    cudaFuncSetAttribute(edge_kernel, cudaFuncAttributeMaxDynamicSharedMemorySize, SMEM_BYTES);

    zero_kernel<<<1024, 256>>>();
    edge_kernel<<<GRID, THREADS, SMEM_BYTES>>>(x, ei, ea, W1, b1, W2, b2, W3, b3, W4, b4);
    finalize_kernel<<<(N_NODES * 4 + 255) / 256, 256>>>(x, root, bias, out);
}